// round 6
// baseline (speedup 1.0000x reference)
#include <cuda_runtime.h>
#include <math.h>
#include <math_constants.h>

#define SEQ   128
#define BATCH 32
#define EMB   32
#define HID   16
#define VOCAB 32000
#define CIN   48           // EMB + HID

#define P1_TILES 32        // 32000 / (256*4) rounded up
#define P2_TILES 32
#define RECUR_BLOCKS 4     // 4 blocks x 8 warps = 32 batches
#define PIPE_DIST 2        // p2(s) scheduled with p1(s + PIPE_DIST)
#define LOG2E 1.4426950408889634f

// Scratch (no allocations allowed)
__device__ float g_H[SEQ * BATCH * HID];
__device__ float g_partS[SEQ * P1_TILES * BATCH];
__device__ float g_logZ[SEQ * BATCH];
__device__ int   g_cntR[SEQ];    // recurrence step completion (0..32)
__device__ int   g_cnt1[SEQ];    // p1 block completion (0..32)
__device__ int   g_ready[SEQ];   // logZ ready flag

// ---- packed f32x2 helpers (Blackwell) --------------------------------------
__device__ __forceinline__ void ffma2(unsigned long long& d,
                                      unsigned long long a,
                                      unsigned long long b) {
    asm("fma.rn.f32x2 %0, %1, %2, %0;" : "+l"(d) : "l"(a), "l"(b));
}
__device__ __forceinline__ float hsum2(unsigned long long v) {
    float lo, hi;
    asm("mov.b64 {%0, %1}, %2;" : "=f"(lo), "=f"(hi) : "l"(v));
    return lo + hi;
}
__device__ __forceinline__ unsigned long long packf2(float lo, float hi) {
    unsigned long long d;
    asm("mov.b64 %0, {%1, %2};" : "=l"(d) : "f"(lo), "f"(hi));
    return d;
}

// ---------------------------------------------------------------------------
// Init: zero the sync flags (runs before the fused kernel every launch).
// ---------------------------------------------------------------------------
__global__ void init_kernel() {
    const int t = threadIdx.x;
    if (t < SEQ) { g_cntR[t] = 0; g_cnt1[t] = 0; g_ready[t] = 0; }
}

// ---------------------------------------------------------------------------
// Role: recurrence. One warp per batch; signals g_cntR[t] per step.
// ---------------------------------------------------------------------------
__device__ __forceinline__ void recur_role(
    int blk, int tid, char* sm,
    const int* __restrict__ idx, const float* __restrict__ h0,
    const float* __restrict__ emb, const float* __restrict__ W_ih,
    const float* __restrict__ b_ih) {
    const int wq   = tid >> 5;
    const int lane = tid & 31;
    const int b    = blk * 8 + wq;
    const int i    = lane & 15;
    const int half = lane >> 4;

    int*   idxs = (int*)sm + wq * SEQ;
    float* comb = (float*)((int*)sm + 8 * SEQ) + wq * CIN;

    for (int t = lane; t < SEQ; t += 32) idxs[t] = idx[t * BATCH + b];

    float wih[24];
    const int base = half * 24;
#pragma unroll
    for (int j = 0; j < 24; j++) wih[j] = W_ih[i * CIN + base + j];
    const float bias = b_ih[i];

    __syncwarp();

    float x = emb[idxs[0] * EMB + lane];
    float h = (lane < 16) ? h0[b * HID + lane] : 0.f;

    for (int t = 0; t < SEQ; t++) {
        comb[lane] = x;
        if (lane < 16) comb[EMB + lane] = h;
        __syncwarp();

        if (t + 1 < SEQ) x = emb[idxs[t + 1] * EMB + lane];

        float a0 = 0.f, a1 = 0.f, a2 = 0.f;
#pragma unroll
        for (int j = 0; j < 24; j += 3) {
            a0 += wih[j]     * comb[base + j];
            a1 += wih[j + 1] * comb[base + j + 1];
            a2 += wih[j + 2] * comb[base + j + 2];
        }
        float part = (a0 + a1) + a2;
        part += __shfl_xor_sync(0xffffffffu, part, 16);

        const float z = part + bias;
        const float e = __expf(2.f * z);
        const float hn = __fdividef(e - 1.f, e + 1.f);

        __syncwarp();                 // WAR before next comb writes
        if (lane < 16) {
            h = hn;
            g_H[(t * BATCH + b) * HID + i] = hn;
        }
        __threadfence();              // release the g_H stores (per lane)
        __syncwarp();
        if (lane == 0) atomicAdd(&g_cntR[t], 1);
    }
}

// ---------------------------------------------------------------------------
// Role: pass 1 (sum-exp over 1024 vocab). Last block per s does the combine
// and releases g_ready[s].
// ---------------------------------------------------------------------------
__device__ __forceinline__ void p1_role(
    int s, int bx, int tid, char* sm,
    const float* __restrict__ W_ho, const float* __restrict__ b_ho) {
    const int warp = tid >> 5;
    const int lane = tid & 31;

    ulonglong2 (*hs)[4] = (ulonglong2(*)[4])sm;
    float (*rS)[BATCH]  = (float(*)[BATCH])(sm + BATCH * 4 * 16);
    __shared__ int s_last;

    // wait for recurrence step s
    if (tid == 0) {
        volatile int* f = g_cntR + s;
        while (*f < BATCH) __nanosleep(64);
        __threadfence();
    }
    __syncthreads();

    if (tid < 128) {
        float4 hv = ((const float4*)(g_H + s * BATCH * HID))[tid];
        hv.x *= LOG2E; hv.y *= LOG2E; hv.z *= LOG2E; hv.w *= LOG2E;
        ((float4*)hs)[tid] = hv;
    }
    __syncthreads();

    const int v0 = (bx * 256 + tid) * 4;
    unsigned long long w[4][8];
    unsigned long long biasp[4];
    if (v0 < VOCAB) {
#pragma unroll
        for (int r = 0; r < 4; r++) {
            const ulonglong2* wp = (const ulonglong2*)(W_ho + (v0 + r) * HID);
            const ulonglong2 wa = wp[0], wb = wp[1], wc = wp[2], wd = wp[3];
            w[r][0] = wa.x; w[r][1] = wa.y; w[r][2] = wb.x; w[r][3] = wb.y;
            w[r][4] = wc.x; w[r][5] = wc.y; w[r][6] = wd.x; w[r][7] = wd.y;
            biasp[r] = packf2(b_ho[v0 + r] * LOG2E, 0.f);
        }
    } else {
#pragma unroll
        for (int r = 0; r < 4; r++) {
#pragma unroll
            for (int k = 0; k < 8; k++) w[r][k] = 0ull;
            biasp[r] = packf2(-1e30f, 0.f);
        }
    }

#pragma unroll
    for (int half = 0; half < 2; half++) {
        float v[16];
#pragma unroll
        for (int j = 0; j < 16; j++) {
            const int b = half * 16 + j;
            const ulonglong2 h01 = hs[b][0], h23 = hs[b][1];
            const ulonglong2 h45 = hs[b][2], h67 = hs[b][3];
            unsigned long long a0 = biasp[0], a1 = biasp[1];
            unsigned long long a2 = biasp[2], a3 = biasp[3];
            ffma2(a0, w[0][0], h01.x); ffma2(a0, w[0][1], h01.y);
            ffma2(a0, w[0][2], h23.x); ffma2(a0, w[0][3], h23.y);
            ffma2(a0, w[0][4], h45.x); ffma2(a0, w[0][5], h45.y);
            ffma2(a0, w[0][6], h67.x); ffma2(a0, w[0][7], h67.y);
            ffma2(a1, w[1][0], h01.x); ffma2(a1, w[1][1], h01.y);
            ffma2(a1, w[1][2], h23.x); ffma2(a1, w[1][3], h23.y);
            ffma2(a1, w[1][4], h45.x); ffma2(a1, w[1][5], h45.y);
            ffma2(a1, w[1][6], h67.x); ffma2(a1, w[1][7], h67.y);
            ffma2(a2, w[2][0], h01.x); ffma2(a2, w[2][1], h01.y);
            ffma2(a2, w[2][2], h23.x); ffma2(a2, w[2][3], h23.y);
            ffma2(a2, w[2][4], h45.x); ffma2(a2, w[2][5], h45.y);
            ffma2(a2, w[2][6], h67.x); ffma2(a2, w[2][7], h67.y);
            ffma2(a3, w[3][0], h01.x); ffma2(a3, w[3][1], h01.y);
            ffma2(a3, w[3][2], h23.x); ffma2(a3, w[3][3], h23.y);
            ffma2(a3, w[3][4], h45.x); ffma2(a3, w[3][5], h45.y);
            ffma2(a3, w[3][6], h67.x); ffma2(a3, w[3][7], h67.y);
            v[j] = (exp2f(hsum2(a0)) + exp2f(hsum2(a1)))
                 + (exp2f(hsum2(a2)) + exp2f(hsum2(a3)));
        }
        // folding butterfly: 16 values -> per-batch totals
#pragma unroll
        for (int j = 0; j < 8; j++) {
            const float send = (lane & 16) ? v[j] : v[j + 8];
            const float recv = __shfl_xor_sync(0xffffffffu, send, 16);
            const float mine = (lane & 16) ? v[j + 8] : v[j];
            v[j] = mine + recv;
        }
#pragma unroll
        for (int j = 0; j < 4; j++) {
            const float send = (lane & 8) ? v[j] : v[j + 4];
            const float recv = __shfl_xor_sync(0xffffffffu, send, 8);
            const float mine = (lane & 8) ? v[j + 4] : v[j];
            v[j] = mine + recv;
        }
#pragma unroll
        for (int j = 0; j < 2; j++) {
            const float send = (lane & 4) ? v[j] : v[j + 2];
            const float recv = __shfl_xor_sync(0xffffffffu, send, 4);
            const float mine = (lane & 4) ? v[j + 2] : v[j];
            v[j] = mine + recv;
        }
        {
            const float send = (lane & 2) ? v[0] : v[1];
            const float recv = __shfl_xor_sync(0xffffffffu, send, 2);
            const float mine = (lane & 2) ? v[1] : v[0];
            v[0] = mine + recv;
        }
        v[0] += __shfl_xor_sync(0xffffffffu, v[0], 1);
        if (!(lane & 1)) rS[warp][half * 16 + ((lane >> 1) & 15)] = v[0];
    }
    __syncthreads();
    if (tid < BATCH) {
        float S = 0.f;
#pragma unroll
        for (int wq = 0; wq < 8; wq++) S += rS[wq][tid];
        g_partS[(s * P1_TILES + bx) * BATCH + tid] = S;
        __threadfence();              // release partial
    }
    __syncthreads();
    if (tid == 0)
        s_last = (atomicAdd(&g_cnt1[s], 1) == P1_TILES - 1);
    __syncthreads();
    if (s_last) {                     // this block folds in the combine
        if (tid < BATCH) {
            float S = 0.f;
            for (int t = 0; t < P1_TILES; t++)
                S += g_partS[(s * P1_TILES + t) * BATCH + tid];
            g_logZ[s * BATCH + tid] = logf(S);
            __threadfence();          // release logZ
        }
        __syncthreads();
        if (tid == 0) atomicExch(&g_ready[s], 1);
    }
}

// ---------------------------------------------------------------------------
// Role: pass 2 (write log-probs for 1024 vocab). Spins on g_ready[s].
// ---------------------------------------------------------------------------
__device__ __forceinline__ void p2_role(
    int s, int bx, int tid, char* sm,
    const float* __restrict__ W_ho, const float* __restrict__ b_ho,
    float* __restrict__ out) {
    ulonglong2 (*hs)[4] = (ulonglong2(*)[4])sm;
    float* lz = (float*)(sm + BATCH * 4 * 16);

    if (tid == 0) {
        volatile int* f = g_ready + s;
        while (*f == 0) __nanosleep(128);
        __threadfence();
    }
    __syncthreads();

    if (tid < 128)
        ((ulonglong2*)hs)[tid] = ((const ulonglong2*)(g_H + s * BATCH * HID))[tid];
    if (tid < 32) lz[tid] = g_logZ[s * BATCH + tid];
    __syncthreads();

    const int v0 = (bx * 256 + tid) * 4;
    if (v0 >= VOCAB) return;

    unsigned long long w[4][8];
    float bias[4];
#pragma unroll
    for (int r = 0; r < 4; r++) {
        const ulonglong2* wp = (const ulonglong2*)(W_ho + (v0 + r) * HID);
        const ulonglong2 wa = wp[0], wb = wp[1], wc = wp[2], wd = wp[3];
        w[r][0] = wa.x; w[r][1] = wa.y; w[r][2] = wb.x; w[r][3] = wb.y;
        w[r][4] = wc.x; w[r][5] = wc.y; w[r][6] = wd.x; w[r][7] = wd.y;
        bias[r] = b_ho[v0 + r];
    }

    float* orow = out + (size_t)s * BATCH * VOCAB + v0;
#pragma unroll 4
    for (int b = 0; b < BATCH; b++) {
        const ulonglong2 h01 = hs[b][0], h23 = hs[b][1];
        const ulonglong2 h45 = hs[b][2], h67 = hs[b][3];
        const float nl = -lz[b];
        unsigned long long a0 = packf2(bias[0], nl);
        unsigned long long a1 = packf2(bias[1], nl);
        unsigned long long a2 = packf2(bias[2], nl);
        unsigned long long a3 = packf2(bias[3], nl);
        ffma2(a0, w[0][0], h01.x); ffma2(a0, w[0][1], h01.y);
        ffma2(a0, w[0][2], h23.x); ffma2(a0, w[0][3], h23.y);
        ffma2(a0, w[0][4], h45.x); ffma2(a0, w[0][5], h45.y);
        ffma2(a0, w[0][6], h67.x); ffma2(a0, w[0][7], h67.y);
        ffma2(a1, w[1][0], h01.x); ffma2(a1, w[1][1], h01.y);
        ffma2(a1, w[1][2], h23.x); ffma2(a1, w[1][3], h23.y);
        ffma2(a1, w[1][4], h45.x); ffma2(a1, w[1][5], h45.y);
        ffma2(a1, w[1][6], h67.x); ffma2(a1, w[1][7], h67.y);
        ffma2(a2, w[2][0], h01.x); ffma2(a2, w[2][1], h01.y);
        ffma2(a2, w[2][2], h23.x); ffma2(a2, w[2][3], h23.y);
        ffma2(a2, w[2][4], h45.x); ffma2(a2, w[2][5], h45.y);
        ffma2(a2, w[2][6], h67.x); ffma2(a2, w[2][7], h67.y);
        ffma2(a3, w[3][0], h01.x); ffma2(a3, w[3][1], h01.y);
        ffma2(a3, w[3][2], h23.x); ffma2(a3, w[3][3], h23.y);
        ffma2(a3, w[3][4], h45.x); ffma2(a3, w[3][5], h45.y);
        ffma2(a3, w[3][6], h67.x); ffma2(a3, w[3][7], h67.y);
        float4 res;
        res.x = hsum2(a0);
        res.y = hsum2(a1);
        res.z = hsum2(a2);
        res.w = hsum2(a3);
        __stcs((float4*)(orow + (size_t)b * VOCAB), res);
    }
}

// ---------------------------------------------------------------------------
// Fused pipeline kernel. bid layout (strictly increasing dependencies):
//   [0, 4)                         : recurrence
//   then 64-bid groups g = 0..129  : r<32 -> p1(s=g)   (if g < 128)
//                                    r>=32 -> p2(s=g-2) (if 0 <= g-2 < 128)
// ---------------------------------------------------------------------------
__global__ __launch_bounds__(256, 2)
void fused_kernel(const int*   __restrict__ idx,
                  const float* __restrict__ h0,
                  const float* __restrict__ emb,
                  const float* __restrict__ W_ih,
                  const float* __restrict__ b_ih,
                  const float* __restrict__ W_ho,
                  const float* __restrict__ b_ho,
                  float* __restrict__ out) {
    __shared__ __align__(16) char sm[6144];
    const int bid = blockIdx.x;
    const int tid = threadIdx.x;

    if (bid < RECUR_BLOCKS) {
        recur_role(bid, tid, sm, idx, h0, emb, W_ih, b_ih);
        return;
    }
    const int gid = bid - RECUR_BLOCKS;
    const int g = gid >> 6;
    const int r = gid & 63;
    if (r < 32) {
        if (g < SEQ) p1_role(g, r, tid, sm, W_ho, b_ho);
    } else {
        const int s = g - PIPE_DIST;
        if (s >= 0 && s < SEQ) p2_role(s, r - 32, tid, sm, W_ho, b_ho, out);
    }
}

// ---------------------------------------------------------------------------
// Launcher. Input order: input_batch, h0, embedding, W_ih, b_ih, W_ho, b_ho.
// ---------------------------------------------------------------------------
extern "C" void kernel_launch(void* const* d_in, const int* in_sizes, int n_in,
                              void* d_out, int out_size) {
    const int*   idx  = (const int*)  d_in[0];
    const float* h0   = (const float*)d_in[1];
    const float* emb  = (const float*)d_in[2];
    const float* W_ih = (const float*)d_in[3];
    const float* b_ih = (const float*)d_in[4];
    const float* W_ho = (const float*)d_in[5];
    const float* b_ho = (const float*)d_in[6];
    float* out = (float*)d_out;

    init_kernel<<<1, 128>>>();
    const int nblocks = RECUR_BLOCKS + (SEQ + PIPE_DIST) * 64;  // 4 + 130*64
    fused_kernel<<<nblocks, 256>>>(idx, h0, emb, W_ih, b_ih, W_ho, b_ho, out);
}

// round 7
// speedup vs baseline: 1.2942x; 1.2942x over previous
#include <cuda_runtime.h>
#include <math.h>
#include <math_constants.h>

#define SEQ   128
#define BATCH 32
#define EMB   32
#define HID   16
#define VOCAB 32000
#define CIN   48           // EMB + HID

#define P1_TILES 32        // ceil(32000 / (256*4))
#define P2_TILES 32
#define LOG2E 1.4426950408889634f

// Scratch (no allocations allowed)
__device__ float g_H[SEQ * BATCH * HID];
__device__ float g_partS[SEQ * P1_TILES * BATCH];
__device__ float g_logZ[SEQ * BATCH];

// ---- packed f32x2 helpers (Blackwell) --------------------------------------
__device__ __forceinline__ void ffma2(unsigned long long& d,
                                      unsigned long long a,
                                      unsigned long long b) {
    asm("fma.rn.f32x2 %0, %1, %2, %0;" : "+l"(d) : "l"(a), "l"(b));
}
__device__ __forceinline__ float hsum2(unsigned long long v) {
    float lo, hi;
    asm("mov.b64 {%0, %1}, %2;" : "=f"(lo), "=f"(hi) : "l"(v));
    return lo + hi;
}
__device__ __forceinline__ unsigned long long packf2(float lo, float hi) {
    unsigned long long d;
    asm("mov.b64 %0, {%1, %2};" : "=l"(d) : "f"(lo), "f"(hi));
    return d;
}
// raw MUFU.EX2 (single instruction, separate pipe from fma)
__device__ __forceinline__ float ex2(float x) {
    float r;
    asm("ex2.approx.f32 %0, %1;" : "=f"(r) : "f"(x));
    return r;
}

// ---------------------------------------------------------------------------
// Kernel A: recurrence. 32 independent single-warp blocks (one per batch).
// ---------------------------------------------------------------------------
__global__ __launch_bounds__(32, 1)
void recur_kernel(const int*   __restrict__ idx,
                  const float* __restrict__ h0,
                  const float* __restrict__ emb,
                  const float* __restrict__ W_ih,
                  const float* __restrict__ b_ih) {
    const int b    = blockIdx.x;
    const int lane = threadIdx.x;
    const int i    = lane & 15;
    const int half = lane >> 4;

    __shared__ int   idxs[SEQ];
    __shared__ float comb[CIN];

    for (int t = lane; t < SEQ; t += 32) idxs[t] = idx[t * BATCH + b];

    float wih[24];
    const int base = half * 24;
#pragma unroll
    for (int j = 0; j < 24; j++) wih[j] = W_ih[i * CIN + base + j];
    const float bias = b_ih[i];

    __syncwarp();

    float x = emb[idxs[0] * EMB + lane];          // EMB == 32 == warp size
    float h = (lane < 16) ? h0[b * HID + lane] : 0.f;

    for (int t = 0; t < SEQ; t++) {
        comb[lane] = x;
        if (lane < 16) comb[EMB + lane] = h;
        __syncwarp();

        if (t + 1 < SEQ) x = emb[idxs[t + 1] * EMB + lane];  // prefetch

        float a0 = 0.f, a1 = 0.f, a2 = 0.f;
#pragma unroll
        for (int j = 0; j < 24; j += 3) {
            a0 += wih[j]     * comb[base + j];
            a1 += wih[j + 1] * comb[base + j + 1];
            a2 += wih[j + 2] * comb[base + j + 2];
        }
        float part = (a0 + a1) + a2;
        part += __shfl_xor_sync(0xffffffffu, part, 16);

        const float z = part + bias;
        const float e = ex2(2.f * LOG2E * z);     // e^{2z}
        const float hn = __fdividef(e - 1.f, e + 1.f);

        __syncwarp();                 // WAR before next comb writes
        if (lane < 16) {
            h = hn;
            g_H[(t * BATCH + b) * HID + i] = hn;
        }
    }
}

// ---------------------------------------------------------------------------
// Kernel B (pass 1): sum-exp of logits. No max needed (|logit| <= 4.25).
// 4 vocab rows per thread in regs, loop over 32 batches (2 halves of 16).
// log2-domain; exp = single MUFU.EX2 (ex2.approx) -- NOT library exp2f.
// ---------------------------------------------------------------------------
__global__ __launch_bounds__(256, 2)
void logits_pass1(const float* __restrict__ W_ho,
                  const float* __restrict__ b_ho) {
    const int s    = blockIdx.y;
    const int bx   = blockIdx.x;
    const int tid  = threadIdx.x;
    const int warp = tid >> 5;
    const int lane = tid & 31;

    __shared__ ulonglong2 hs[BATCH][4];
    __shared__ float rS[8][BATCH];
    if (tid < 128) {
        float4 hv = ((const float4*)(g_H + s * BATCH * HID))[tid];
        hv.x *= LOG2E; hv.y *= LOG2E; hv.z *= LOG2E; hv.w *= LOG2E;
        ((float4*)hs)[tid] = hv;
    }
    __syncthreads();

    const int v0 = (bx * 256 + tid) * 4;
    unsigned long long w[4][8];
    unsigned long long biasp[4];
    if (v0 < VOCAB) {   // VOCAB % 1024 == 256-thread*4 tiles: uniform
#pragma unroll
        for (int r = 0; r < 4; r++) {
            const ulonglong2* wp = (const ulonglong2*)(W_ho + (v0 + r) * HID);
            const ulonglong2 wa = wp[0], wb = wp[1], wc = wp[2], wd = wp[3];
            w[r][0] = wa.x; w[r][1] = wa.y; w[r][2] = wb.x; w[r][3] = wb.y;
            w[r][4] = wc.x; w[r][5] = wc.y; w[r][6] = wd.x; w[r][7] = wd.y;
            biasp[r] = packf2(b_ho[v0 + r] * LOG2E, 0.f);
        }
    } else {
#pragma unroll
        for (int r = 0; r < 4; r++) {
#pragma unroll
            for (int k = 0; k < 8; k++) w[r][k] = 0ull;
            biasp[r] = packf2(-126.f, 0.f);   // ex2 -> ~0
        }
    }

#pragma unroll
    for (int half = 0; half < 2; half++) {
        float v[16];
#pragma unroll
        for (int j = 0; j < 16; j++) {
            const int b = half * 16 + j;
            const ulonglong2 h01 = hs[b][0], h23 = hs[b][1];
            const ulonglong2 h45 = hs[b][2], h67 = hs[b][3];
            unsigned long long a0 = biasp[0], a1 = biasp[1];
            unsigned long long a2 = biasp[2], a3 = biasp[3];
            ffma2(a0, w[0][0], h01.x); ffma2(a0, w[0][1], h01.y);
            ffma2(a0, w[0][2], h23.x); ffma2(a0, w[0][3], h23.y);
            ffma2(a0, w[0][4], h45.x); ffma2(a0, w[0][5], h45.y);
            ffma2(a0, w[0][6], h67.x); ffma2(a0, w[0][7], h67.y);
            ffma2(a1, w[1][0], h01.x); ffma2(a1, w[1][1], h01.y);
            ffma2(a1, w[1][2], h23.x); ffma2(a1, w[1][3], h23.y);
            ffma2(a1, w[1][4], h45.x); ffma2(a1, w[1][5], h45.y);
            ffma2(a1, w[1][6], h67.x); ffma2(a1, w[1][7], h67.y);
            ffma2(a2, w[2][0], h01.x); ffma2(a2, w[2][1], h01.y);
            ffma2(a2, w[2][2], h23.x); ffma2(a2, w[2][3], h23.y);
            ffma2(a2, w[2][4], h45.x); ffma2(a2, w[2][5], h45.y);
            ffma2(a2, w[2][6], h67.x); ffma2(a2, w[2][7], h67.y);
            ffma2(a3, w[3][0], h01.x); ffma2(a3, w[3][1], h01.y);
            ffma2(a3, w[3][2], h23.x); ffma2(a3, w[3][3], h23.y);
            ffma2(a3, w[3][4], h45.x); ffma2(a3, w[3][5], h45.y);
            ffma2(a3, w[3][6], h67.x); ffma2(a3, w[3][7], h67.y);
            v[j] = (ex2(hsum2(a0)) + ex2(hsum2(a1)))
                 + (ex2(hsum2(a2)) + ex2(hsum2(a3)));
        }
        // folding butterfly: 16 values -> per-batch totals in 16 shfls
#pragma unroll
        for (int j = 0; j < 8; j++) {
            const float send = (lane & 16) ? v[j] : v[j + 8];
            const float recv = __shfl_xor_sync(0xffffffffu, send, 16);
            const float mine = (lane & 16) ? v[j + 8] : v[j];
            v[j] = mine + recv;
        }
#pragma unroll
        for (int j = 0; j < 4; j++) {
            const float send = (lane & 8) ? v[j] : v[j + 4];
            const float recv = __shfl_xor_sync(0xffffffffu, send, 8);
            const float mine = (lane & 8) ? v[j + 4] : v[j];
            v[j] = mine + recv;
        }
#pragma unroll
        for (int j = 0; j < 2; j++) {
            const float send = (lane & 4) ? v[j] : v[j + 2];
            const float recv = __shfl_xor_sync(0xffffffffu, send, 4);
            const float mine = (lane & 4) ? v[j + 2] : v[j];
            v[j] = mine + recv;
        }
        {
            const float send = (lane & 2) ? v[0] : v[1];
            const float recv = __shfl_xor_sync(0xffffffffu, send, 2);
            const float mine = (lane & 2) ? v[1] : v[0];
            v[0] = mine + recv;
        }
        v[0] += __shfl_xor_sync(0xffffffffu, v[0], 1);
        if (!(lane & 1)) rS[warp][half * 16 + ((lane >> 1) & 15)] = v[0];
    }
    __syncthreads();
    if (tid < BATCH) {
        float S = 0.f;
#pragma unroll
        for (int wq = 0; wq < 8; wq++) S += rS[wq][tid];
        g_partS[(s * P1_TILES + bx) * BATCH + tid] = S;
    }
}

// ---------------------------------------------------------------------------
// Kernel C: combine tile partials -> logZ per (s, b) row. 4096 threads.
// ---------------------------------------------------------------------------
__global__ void combine_kernel() {
    const int id = blockIdx.x * blockDim.x + threadIdx.x;  // 0..4095
    const int s = id >> 5;
    const int b = id & 31;
    float S = 0.f;
#pragma unroll
    for (int t = 0; t < P1_TILES; t++) S += g_partS[(s * P1_TILES + t) * BATCH + b];
    g_logZ[id] = __logf(S);
}

// ---------------------------------------------------------------------------
// Kernel D (pass 2): recompute logits, write logit - logZ.
// 4 vocab/thread, STG.128. Acc init = pack(bias, -logZ): hsum2 yields the
// final value directly.
// ---------------------------------------------------------------------------
__global__ __launch_bounds__(256, 2)
void logits_pass2(const float* __restrict__ W_ho,
                  const float* __restrict__ b_ho,
                  float* __restrict__ out) {
    const int s   = blockIdx.y;
    const int tid = threadIdx.x;

    __shared__ ulonglong2 hs[BATCH][4];
    __shared__ float      lz[BATCH];
    if (tid < 128)
        ((ulonglong2*)hs)[tid] = ((const ulonglong2*)(g_H + s * BATCH * HID))[tid];
    if (tid < 32) lz[tid] = g_logZ[s * BATCH + tid];
    __syncthreads();

    const int v0 = (blockIdx.x * 256 + tid) * 4;
    if (v0 >= VOCAB) return;

    unsigned long long w[4][8];
    float bias[4];
#pragma unroll
    for (int r = 0; r < 4; r++) {
        const ulonglong2* wp = (const ulonglong2*)(W_ho + (v0 + r) * HID);
        const ulonglong2 wa = wp[0], wb = wp[1], wc = wp[2], wd = wp[3];
        w[r][0] = wa.x; w[r][1] = wa.y; w[r][2] = wb.x; w[r][3] = wb.y;
        w[r][4] = wc.x; w[r][5] = wc.y; w[r][6] = wd.x; w[r][7] = wd.y;
        bias[r] = b_ho[v0 + r];
    }

    float* orow = out + (size_t)s * BATCH * VOCAB + v0;
#pragma unroll 4
    for (int b = 0; b < BATCH; b++) {
        const ulonglong2 h01 = hs[b][0], h23 = hs[b][1];
        const ulonglong2 h45 = hs[b][2], h67 = hs[b][3];
        const float nl = -lz[b];
        unsigned long long a0 = packf2(bias[0], nl);
        unsigned long long a1 = packf2(bias[1], nl);
        unsigned long long a2 = packf2(bias[2], nl);
        unsigned long long a3 = packf2(bias[3], nl);
        ffma2(a0, w[0][0], h01.x); ffma2(a0, w[0][1], h01.y);
        ffma2(a0, w[0][2], h23.x); ffma2(a0, w[0][3], h23.y);
        ffma2(a0, w[0][4], h45.x); ffma2(a0, w[0][5], h45.y);
        ffma2(a0, w[0][6], h67.x); ffma2(a0, w[0][7], h67.y);
        ffma2(a1, w[1][0], h01.x); ffma2(a1, w[1][1], h01.y);
        ffma2(a1, w[1][2], h23.x); ffma2(a1, w[1][3], h23.y);
        ffma2(a1, w[1][4], h45.x); ffma2(a1, w[1][5], h45.y);
        ffma2(a1, w[1][6], h67.x); ffma2(a1, w[1][7], h67.y);
        ffma2(a2, w[2][0], h01.x); ffma2(a2, w[2][1], h01.y);
        ffma2(a2, w[2][2], h23.x); ffma2(a2, w[2][3], h23.y);
        ffma2(a2, w[2][4], h45.x); ffma2(a2, w[2][5], h45.y);
        ffma2(a2, w[2][6], h67.x); ffma2(a2, w[2][7], h67.y);
        ffma2(a3, w[3][0], h01.x); ffma2(a3, w[3][1], h01.y);
        ffma2(a3, w[3][2], h23.x); ffma2(a3, w[3][3], h23.y);
        ffma2(a3, w[3][4], h45.x); ffma2(a3, w[3][5], h45.y);
        ffma2(a3, w[3][6], h67.x); ffma2(a3, w[3][7], h67.y);
        float4 res;
        res.x = hsum2(a0);
        res.y = hsum2(a1);
        res.z = hsum2(a2);
        res.w = hsum2(a3);
        __stcs((float4*)(orow + (size_t)b * VOCAB), res);
    }
}

// ---------------------------------------------------------------------------
// Launcher. Input order: input_batch, h0, embedding, W_ih, b_ih, W_ho, b_ho.
// ---------------------------------------------------------------------------
extern "C" void kernel_launch(void* const* d_in, const int* in_sizes, int n_in,
                              void* d_out, int out_size) {
    const int*   idx  = (const int*)  d_in[0];
    const float* h0   = (const float*)d_in[1];
    const float* emb  = (const float*)d_in[2];
    const float* W_ih = (const float*)d_in[3];
    const float* b_ih = (const float*)d_in[4];
    const float* W_ho = (const float*)d_in[5];
    const float* b_ho = (const float*)d_in[6];
    float* out = (float*)d_out;

    recur_kernel<<<BATCH, 32>>>(idx, h0, emb, W_ih, b_ih);
    logits_pass1<<<dim3(P1_TILES, SEQ), 256>>>(W_ho, b_ho);
    combine_kernel<<<16, 256>>>();
    logits_pass2<<<dim3(P2_TILES, SEQ), 256>>>(W_ho, b_ho, out);
}